// round 1
// baseline (speedup 1.0000x reference)
#include <cuda_runtime.h>

#define N_NODES 50000
#define N_EDGES 300000
#define D 256
#define F_IN 11

// ---------------- scratch (static device allocations; no runtime alloc) ---------
__device__ __align__(16) float g_a[(size_t)N_NODES * D];   // activations in
__device__ __align__(16) float g_b[(size_t)N_NODES * D];   // h @ W
__device__ float g_dis[N_NODES];                            // deg^{-1/2}
__device__ int   g_cnt[N_NODES];
__device__ int   g_rowptr[N_NODES + 1];
__device__ int   g_cursor[N_NODES];
__device__ int   g_col[N_EDGES];

// ---------------- CSR build -----------------------------------------------------
__global__ void k_zero_cnt() {
    int i = blockIdx.x * blockDim.x + threadIdx.x;
    if (i < N_NODES) g_cnt[i] = 0;
}

__global__ void k_count(const int* __restrict__ ei) {
    int e = blockIdx.x * blockDim.x + threadIdx.x;
    if (e < N_EDGES) atomicAdd(&g_cnt[ei[N_EDGES + e]], 1);   // dst row
}

// single-block scan over 50000 counts; also finalizes deg_inv_sqrt (deg = cnt+1, self-loop)
__global__ void k_scan() {
    __shared__ int part[1024];
    int t = threadIdx.x;
    const int CH = (N_NODES + 1023) / 1024;   // 49
    int lo = t * CH;
    int hi = min(lo + CH, N_NODES);
    int s = 0;
    for (int i = lo; i < hi; i++) s += g_cnt[i];
    part[t] = s;
    __syncthreads();
    for (int off = 1; off < 1024; off <<= 1) {
        int tmp = (t >= off) ? part[t - off] : 0;
        __syncthreads();
        part[t] += tmp;
        __syncthreads();
    }
    int run = part[t] - s;   // exclusive prefix of this chunk
    for (int i = lo; i < hi; i++) {
        g_rowptr[i] = run;
        g_cursor[i] = run;
        int c = g_cnt[i];
        g_dis[i] = rsqrtf((float)(c + 1));
        run += c;
    }
    if (t == 0) g_rowptr[N_NODES] = N_EDGES;
}

__global__ void k_fill(const int* __restrict__ ei) {
    int e = blockIdx.x * blockDim.x + threadIdx.x;
    if (e < N_EDGES) {
        int d = ei[N_EDGES + e];
        int p = atomicAdd(&g_cursor[d], 1);
        g_col[p] = ei[e];               // src index
    }
}

// ---------------- embed: g_a = relu(x @ W_embed + b) ----------------------------
#define EMB_NODES 8
__global__ __launch_bounds__(256) void k_embed(const float* __restrict__ x,
                                               const float* __restrict__ W,
                                               const float* __restrict__ b) {
    __shared__ float Ws[F_IN * D];
    __shared__ float xs[EMB_NODES * F_IN];
    int t = threadIdx.x;
    for (int i = t; i < F_IN * D; i += 256) Ws[i] = W[i];
    int n0 = blockIdx.x * EMB_NODES;
    for (int i = t; i < EMB_NODES * F_IN; i += 256) {
        int node = n0 + i / F_IN;
        xs[i] = (node < N_NODES) ? x[(size_t)node * F_IN + (i % F_IN)] : 0.0f;
    }
    __syncthreads();
    float bv = b[t];
    #pragma unroll 1
    for (int j = 0; j < EMB_NODES; j++) {
        int node = n0 + j;
        if (node >= N_NODES) break;
        float acc = bv;
        #pragma unroll
        for (int k = 0; k < F_IN; k++) acc += xs[j * F_IN + k] * Ws[k * D + t];
        g_a[(size_t)node * D + t] = fmaxf(acc, 0.0f);
    }
}

// ---------------- GEMM: g_b = g_a @ Bw  (M=50000, K=N=256) ----------------------
#define BM 128
#define BN 128
#define BK 8
__global__ __launch_bounds__(256) void k_gemm(const float* __restrict__ Bw) {
    __shared__ float As[BK][BM + 4];
    __shared__ float Bs[BK][BN];
    const float* A = g_a;
    float* C = g_b;
    int m0 = blockIdx.y * BM;
    int n0 = blockIdx.x * BN;
    int t = threadIdx.x;
    int arow = t >> 1, ac = (t & 1) * 4;       // A tile: 128 rows x 8 k
    int brow = t >> 5, bc = (t & 31) * 4;      // B tile: 8 k x 128 n
    int ty = t >> 4, tx = t & 15;
    float acc[8][8];
    #pragma unroll
    for (int i = 0; i < 8; i++)
        #pragma unroll
        for (int j = 0; j < 8; j++) acc[i][j] = 0.0f;

    bool avalid = (m0 + arow) < N_NODES;
    const float* Ap = A + (size_t)(m0 + arow) * 256 + ac;

    for (int k0 = 0; k0 < 256; k0 += BK) {
        float4 av = avalid ? *(const float4*)(Ap + k0) : make_float4(0.f, 0.f, 0.f, 0.f);
        float4 bv = *(const float4*)(Bw + (size_t)(k0 + brow) * 256 + n0 + bc);
        As[ac + 0][arow] = av.x;
        As[ac + 1][arow] = av.y;
        As[ac + 2][arow] = av.z;
        As[ac + 3][arow] = av.w;
        *(float4*)&Bs[brow][bc] = bv;
        __syncthreads();
        #pragma unroll
        for (int kk = 0; kk < BK; kk++) {
            float a[8], bvv[8];
            #pragma unroll
            for (int i = 0; i < 8; i++) a[i] = As[kk][ty * 8 + i];
            #pragma unroll
            for (int j = 0; j < 8; j++) bvv[j] = Bs[kk][tx * 8 + j];
            #pragma unroll
            for (int i = 0; i < 8; i++)
                #pragma unroll
                for (int j = 0; j < 8; j++) acc[i][j] += a[i] * bvv[j];
        }
        __syncthreads();
    }
    #pragma unroll
    for (int i = 0; i < 8; i++) {
        int m = m0 + ty * 8 + i;
        if (m < N_NODES) {
            float4* cp = (float4*)(C + (size_t)m * 256 + n0 + tx * 8);
            cp[0] = make_float4(acc[i][0], acc[i][1], acc[i][2], acc[i][3]);
            cp[1] = make_float4(acc[i][4], acc[i][5], acc[i][6], acc[i][7]);
        }
    }
}

// ---------------- aggregation: gather over CSR, fused bias+selfloop+relu --------
// out[i] = bias + dis[i]^2 * hw[i] + sum_{e: dst=i} dis[i]*dis[src] * hw[src]
template<bool RELU, bool TO_GA>
__global__ __launch_bounds__(256) void k_agg(const float* __restrict__ bias,
                                             float* __restrict__ out_ext) {
    int gw = (blockIdx.x * 256 + threadIdx.x) >> 5;   // node = warp id
    int lane = threadIdx.x & 31;
    if (gw >= N_NODES) return;
    const float* hw = g_b;
    float* out = TO_GA ? g_a : out_ext;
    float dd = g_dis[gw];
    int c0 = lane * 8;
    const float4* hp = (const float4*)(hw + (size_t)gw * D + c0);
    float4 h0 = hp[0], h1 = hp[1];
    float4 bb0 = *(const float4*)(bias + c0);
    float4 bb1 = *(const float4*)(bias + c0 + 4);
    float sw = dd * dd;
    float a0 = bb0.x + h0.x * sw, a1 = bb0.y + h0.y * sw;
    float a2 = bb0.z + h0.z * sw, a3 = bb0.w + h0.w * sw;
    float a4 = bb1.x + h1.x * sw, a5 = bb1.y + h1.y * sw;
    float a6 = bb1.z + h1.z * sw, a7 = bb1.w + h1.w * sw;
    int e1 = g_rowptr[gw + 1];
    for (int e = g_rowptr[gw]; e < e1; e++) {
        int s = g_col[e];
        float w = dd * g_dis[s];
        const float4* p = (const float4*)(hw + (size_t)s * D + c0);
        float4 v0 = p[0], v1 = p[1];
        a0 += v0.x * w; a1 += v0.y * w; a2 += v0.z * w; a3 += v0.w * w;
        a4 += v1.x * w; a5 += v1.y * w; a6 += v1.z * w; a7 += v1.w * w;
    }
    if (RELU) {
        a0 = fmaxf(a0, 0.f); a1 = fmaxf(a1, 0.f); a2 = fmaxf(a2, 0.f); a3 = fmaxf(a3, 0.f);
        a4 = fmaxf(a4, 0.f); a5 = fmaxf(a5, 0.f); a6 = fmaxf(a6, 0.f); a7 = fmaxf(a7, 0.f);
    }
    float4* op = (float4*)(out + (size_t)gw * D + c0);
    op[0] = make_float4(a0, a1, a2, a3);
    op[1] = make_float4(a4, a5, a6, a7);
}

// ---------------- launch --------------------------------------------------------
extern "C" void kernel_launch(void* const* d_in, const int* in_sizes, int n_in,
                              void* d_out, int out_size) {
    const float* x       = (const float*)d_in[0];
    const int*   ei      = (const int*)d_in[1];
    const float* W_embed = (const float*)d_in[2];
    const float* b_embed = (const float*)d_in[3];
    const float* W1      = (const float*)d_in[4];
    const float* b1      = (const float*)d_in[5];
    const float* W2      = (const float*)d_in[6];
    const float* b2      = (const float*)d_in[7];
    float* out = (float*)d_out;

    // CSR + normalization (recomputed every call: deterministic work contract)
    k_zero_cnt<<<(N_NODES + 255) / 256, 256>>>();
    k_count<<<(N_EDGES + 255) / 256, 256>>>(ei);
    k_scan<<<1, 1024>>>();
    k_fill<<<(N_EDGES + 255) / 256, 256>>>(ei);

    // embed
    k_embed<<<(N_NODES + EMB_NODES - 1) / EMB_NODES, 256>>>(x, W_embed, b_embed);

    dim3 ggrid(D / BN, (N_NODES + BM - 1) / BM);
    int agg_blocks = (N_NODES * 32 + 255) / 256;

    // layer 1: g_b = g_a @ W1 ; g_a = relu(agg(g_b) + b1)
    k_gemm<<<ggrid, 256>>>(W1);
    k_agg<true, true><<<agg_blocks, 256>>>(b1, nullptr);

    // layer 2: g_b = g_a @ W2 ; out = agg(g_b) + b2
    k_gemm<<<ggrid, 256>>>(W2);
    k_agg<false, false><<<agg_blocks, 256>>>(b2, out);
}

// round 3
// speedup vs baseline: 1.2633x; 1.2633x over previous
#include <cuda_runtime.h>

#define N_NODES 50000
#define N_EDGES 300000
#define D 256
#define F_IN 11

// ---------------- scratch (static device allocations; no runtime alloc) ---------
__device__ __align__(16) float g_a[(size_t)N_NODES * D];   // activations in
__device__ __align__(16) float g_b[(size_t)N_NODES * D];   // h @ W
__device__ float g_dis[N_NODES];                            // deg^{-1/2}
__device__ int   g_cnt[N_NODES];
__device__ int   g_rowptr[N_NODES + 1];
__device__ int   g_cursor[N_NODES];
__device__ int   g_col[N_EDGES];
// pre-split weights (tf32 hi/lo), [layer][256*256]
__device__ __align__(16) float g_Whi[2][D * D];
__device__ __align__(16) float g_Wlo[2][D * D];

// ---------------- tf32 helpers --------------------------------------------------
__device__ __forceinline__ unsigned tf32u(float x) {
    unsigned u;
    asm("cvt.rna.tf32.f32 %0, %1;" : "=r"(u) : "f"(x));
    return u;
}

__device__ __forceinline__ void mma8(float* c, const unsigned* a, unsigned b0, unsigned b1) {
    asm("mma.sync.aligned.m16n8k8.row.col.f32.tf32.tf32.f32 "
        "{%0,%1,%2,%3}, {%4,%5,%6,%7}, {%8,%9}, {%0,%1,%2,%3};"
        : "+f"(c[0]), "+f"(c[1]), "+f"(c[2]), "+f"(c[3])
        : "r"(a[0]), "r"(a[1]), "r"(a[2]), "r"(a[3]), "r"(b0), "r"(b1));
}

// ---------------- weight split: hi/lo tf32 decomposition ------------------------
__global__ void k_split(const float* __restrict__ W1, const float* __restrict__ W2) {
    int i = blockIdx.x * 256 + threadIdx.x;
    if (i < D * D) {
        float w1 = W1[i];
        float h1 = __uint_as_float(tf32u(w1));
        g_Whi[0][i] = h1;
        g_Wlo[0][i] = __uint_as_float(tf32u(w1 - h1));
        float w2 = W2[i];
        float h2 = __uint_as_float(tf32u(w2));
        g_Whi[1][i] = h2;
        g_Wlo[1][i] = __uint_as_float(tf32u(w2 - h2));
    }
}

// ---------------- CSR build -----------------------------------------------------
__global__ void k_zero_cnt() {
    int i = blockIdx.x * blockDim.x + threadIdx.x;
    if (i < N_NODES) g_cnt[i] = 0;
}

__global__ void k_count(const int* __restrict__ ei) {
    int e = blockIdx.x * blockDim.x + threadIdx.x;
    if (e < N_EDGES) atomicAdd(&g_cnt[ei[N_EDGES + e]], 1);   // dst row
}

// single-block scan over 50000 counts; also finalizes deg_inv_sqrt (deg = cnt+1)
__global__ void k_scan() {
    __shared__ int part[1024];
    int t = threadIdx.x;
    const int CH = (N_NODES + 1023) / 1024;   // 49
    int lo = t * CH;
    int hi = min(lo + CH, N_NODES);
    int s = 0;
    for (int i = lo; i < hi; i++) s += g_cnt[i];
    part[t] = s;
    __syncthreads();
    for (int off = 1; off < 1024; off <<= 1) {
        int tmp = (t >= off) ? part[t - off] : 0;
        __syncthreads();
        part[t] += tmp;
        __syncthreads();
    }
    int run = part[t] - s;   // exclusive prefix of this chunk
    for (int i = lo; i < hi; i++) {
        g_rowptr[i] = run;
        g_cursor[i] = run;
        int c = g_cnt[i];
        g_dis[i] = rsqrtf((float)(c + 1));
        run += c;
    }
    if (t == 0) g_rowptr[N_NODES] = N_EDGES;
}

__global__ void k_fill(const int* __restrict__ ei) {
    int e = blockIdx.x * blockDim.x + threadIdx.x;
    if (e < N_EDGES) {
        int d = ei[N_EDGES + e];
        int p = atomicAdd(&g_cursor[d], 1);
        g_col[p] = ei[e];               // src index
    }
}

// ---------------- embed: g_a = relu(x @ W_embed + b) ----------------------------
#define EMB_NODES 8
__global__ __launch_bounds__(256) void k_embed(const float* __restrict__ x,
                                               const float* __restrict__ W,
                                               const float* __restrict__ b) {
    __shared__ float Ws[F_IN * D];
    __shared__ float xs[EMB_NODES * F_IN];
    int t = threadIdx.x;
    for (int i = t; i < F_IN * D; i += 256) Ws[i] = W[i];
    int n0 = blockIdx.x * EMB_NODES;
    for (int i = t; i < EMB_NODES * F_IN; i += 256) {
        int node = n0 + i / F_IN;
        xs[i] = (node < N_NODES) ? x[(size_t)node * F_IN + (i % F_IN)] : 0.0f;
    }
    __syncthreads();
    float bv = b[t];
    #pragma unroll 1
    for (int j = 0; j < EMB_NODES; j++) {
        int node = n0 + j;
        if (node >= N_NODES) break;
        float acc = bv;
        #pragma unroll
        for (int k = 0; k < F_IN; k++) acc += xs[j * F_IN + k] * Ws[k * D + t];
        g_a[(size_t)node * D + t] = fmaxf(acc, 0.0f);
    }
}

// ---------------- tensor-core GEMM: g_b = g_a @ W (3xTF32) ----------------------
// tile: 128(M) x 128(N), BK=8, 8 warps = 4(M) x 2(N), warp tile 32x64.
#define GBM 128
#define GBN 128
#define AS_STRIDE 9
#define BS_STRIDE 136

__global__ __launch_bounds__(256, 2) void k_gemm_tc(const float* __restrict__ Whi,
                                                    const float* __restrict__ Wlo) {
    __shared__ float As[2][GBM][AS_STRIDE];
    __shared__ float Bh[2][8][BS_STRIDE];
    __shared__ float Bl[2][8][BS_STRIDE];

    int t = threadIdx.x;
    int m0 = blockIdx.y * GBM;
    int n0 = blockIdx.x * GBN;
    int wid = t >> 5, lane = t & 31;
    int g = lane >> 2, tg = lane & 3;
    int wm = wid & 3;        // 0..3 -> M offset wm*32
    int wn = wid >> 2;       // 0..1 -> N offset wn*64

    float C[2][8][4];
    #pragma unroll
    for (int it = 0; it < 2; it++)
        #pragma unroll
        for (int jt = 0; jt < 8; jt++)
            #pragma unroll
            for (int q = 0; q < 4; q++) C[it][jt][q] = 0.0f;

    // staging indices
    int ar = t >> 1, acg = (t & 1) * 4;     // A: 128 rows x 8 k
    int br = t >> 5, bcg = (t & 31) * 4;    // B: 8 k x 128 n
    bool aval = (m0 + ar) < N_NODES;
    const float* Ap = g_a + (size_t)(m0 + ar) * D + acg;
    const float* Bph = Whi + n0 + bcg;
    const float* Bpl = Wlo + n0 + bcg;

    // prologue: load chunk 0
    {
        float4 av = aval ? *(const float4*)(Ap) : make_float4(0.f, 0.f, 0.f, 0.f);
        float4 bh4 = *(const float4*)(Bph + (size_t)br * D);
        float4 bl4 = *(const float4*)(Bpl + (size_t)br * D);
        As[0][ar][acg + 0] = av.x; As[0][ar][acg + 1] = av.y;
        As[0][ar][acg + 2] = av.z; As[0][ar][acg + 3] = av.w;
        *(float4*)&Bh[0][br][bcg] = bh4;
        *(float4*)&Bl[0][br][bcg] = bl4;
    }
    __syncthreads();

    int p = 0;
    #pragma unroll 1
    for (int c = 0; c < 32; c++) {
        // prefetch chunk c+1 into registers
        float4 av, bh4, bl4;
        if (c < 31) {
            int k = (c + 1) * 8;
            av = aval ? *(const float4*)(Ap + k) : make_float4(0.f, 0.f, 0.f, 0.f);
            bh4 = *(const float4*)(Bph + (size_t)(k + br) * D);
            bl4 = *(const float4*)(Bpl + (size_t)(k + br) * D);
        }

        // load + split A fragments (2 m-tiles)
        unsigned ahi[2][4], alo[2][4];
        #pragma unroll
        for (int it = 0; it < 2; it++) {
            int r0 = wm * 32 + it * 16;
            float a0 = As[p][r0 + g][tg];
            float a1 = As[p][r0 + 8 + g][tg];
            float a2 = As[p][r0 + g][tg + 4];
            float a3 = As[p][r0 + 8 + g][tg + 4];
            ahi[it][0] = tf32u(a0); alo[it][0] = tf32u(a0 - __uint_as_float(ahi[it][0]));
            ahi[it][1] = tf32u(a1); alo[it][1] = tf32u(a1 - __uint_as_float(ahi[it][1]));
            ahi[it][2] = tf32u(a2); alo[it][2] = tf32u(a2 - __uint_as_float(ahi[it][2]));
            ahi[it][3] = tf32u(a3); alo[it][3] = tf32u(a3 - __uint_as_float(ahi[it][3]));
        }

        // per n-tile: load B frags (hi/lo), 3 mmas per m-tile
        #pragma unroll
        for (int jt = 0; jt < 8; jt++) {
            int col = wn * 64 + jt * 8 + g;
            unsigned bh0 = __float_as_uint(Bh[p][tg][col]);
            unsigned bh1 = __float_as_uint(Bh[p][tg + 4][col]);
            unsigned bl0 = __float_as_uint(Bl[p][tg][col]);
            unsigned bl1 = __float_as_uint(Bl[p][tg + 4][col]);
            #pragma unroll
            for (int it = 0; it < 2; it++) {
                mma8(C[it][jt], ahi[it], bh0, bh1);
                mma8(C[it][jt], ahi[it], bl0, bl1);
                mma8(C[it][jt], alo[it], bh0, bh1);
            }
        }

        if (c < 31) {
            int np = p ^ 1;
            As[np][ar][acg + 0] = av.x; As[np][ar][acg + 1] = av.y;
            As[np][ar][acg + 2] = av.z; As[np][ar][acg + 3] = av.w;
            *(float4*)&Bh[np][br][bcg] = bh4;
            *(float4*)&Bl[np][br][bcg] = bl4;
            __syncthreads();
            p = np;
        }
    }

    // epilogue
    #pragma unroll
    for (int it = 0; it < 2; it++) {
        int r0 = m0 + wm * 32 + it * 16 + g;
        #pragma unroll
        for (int jt = 0; jt < 8; jt++) {
            int col = n0 + wn * 64 + jt * 8 + 2 * tg;
            if (r0 < N_NODES)
                *(float2*)(g_b + (size_t)r0 * D + col) = make_float2(C[it][jt][0], C[it][jt][1]);
            if (r0 + 8 < N_NODES)
                *(float2*)(g_b + (size_t)(r0 + 8) * D + col) = make_float2(C[it][jt][2], C[it][jt][3]);
        }
    }
}

// ---------------- aggregation: gather over CSR, fused bias+selfloop+relu --------
// out[i] = bias + dis[i]^2 * hw[i] + sum_{e: dst=i} dis[i]*dis[src] * hw[src]
template<bool RELU, bool TO_GA>
__global__ __launch_bounds__(256) void k_agg(const float* __restrict__ bias,
                                             float* __restrict__ out_ext) {
    int gw = (blockIdx.x * 256 + threadIdx.x) >> 5;   // node = warp id
    int lane = threadIdx.x & 31;
    if (gw >= N_NODES) return;
    const float* hw = g_b;
    float* out = TO_GA ? g_a : out_ext;
    float dd = g_dis[gw];
    int c0 = lane * 8;
    const float4* hp = (const float4*)(hw + (size_t)gw * D + c0);
    float4 h0 = hp[0], h1 = hp[1];
    float4 bb0 = *(const float4*)(bias + c0);
    float4 bb1 = *(const float4*)(bias + c0 + 4);
    float sw = dd * dd;
    float a0 = bb0.x + h0.x * sw, a1 = bb0.y + h0.y * sw;
    float a2 = bb0.z + h0.z * sw, a3 = bb0.w + h0.w * sw;
    float a4 = bb1.x + h1.x * sw, a5 = bb1.y + h1.y * sw;
    float a6 = bb1.z + h1.z * sw, a7 = bb1.w + h1.w * sw;
    int e1 = g_rowptr[gw + 1];
    for (int e = g_rowptr[gw]; e < e1; e++) {
        int s = g_col[e];
        float w = dd * g_dis[s];
        const float4* pp = (const float4*)(hw + (size_t)s * D + c0);
        float4 v0 = pp[0], v1 = pp[1];
        a0 += v0.x * w; a1 += v0.y * w; a2 += v0.z * w; a3 += v0.w * w;
        a4 += v1.x * w; a5 += v1.y * w; a6 += v1.z * w; a7 += v1.w * w;
    }
    if (RELU) {
        a0 = fmaxf(a0, 0.f); a1 = fmaxf(a1, 0.f); a2 = fmaxf(a2, 0.f); a3 = fmaxf(a3, 0.f);
        a4 = fmaxf(a4, 0.f); a5 = fmaxf(a5, 0.f); a6 = fmaxf(a6, 0.f); a7 = fmaxf(a7, 0.f);
    }
    float4* op = (float4*)(out + (size_t)gw * D + c0);
    op[0] = make_float4(a0, a1, a2, a3);
    op[1] = make_float4(a4, a5, a6, a7);
}

// ---------------- launch --------------------------------------------------------
extern "C" void kernel_launch(void* const* d_in, const int* in_sizes, int n_in,
                              void* d_out, int out_size) {
    const float* x       = (const float*)d_in[0];
    const int*   ei      = (const int*)d_in[1];
    const float* W_embed = (const float*)d_in[2];
    const float* b_embed = (const float*)d_in[3];
    const float* W1      = (const float*)d_in[4];
    const float* b1      = (const float*)d_in[5];
    const float* W2      = (const float*)d_in[6];
    const float* b2      = (const float*)d_in[7];
    float* out = (float*)d_out;

    // CSR + normalization
    k_zero_cnt<<<(N_NODES + 255) / 256, 256>>>();
    k_count<<<(N_EDGES + 255) / 256, 256>>>(ei);
    k_scan<<<1, 1024>>>();
    k_fill<<<(N_EDGES + 255) / 256, 256>>>(ei);

    // weight hi/lo split + embed
    k_split<<<(D * D + 255) / 256, 256>>>(W1, W2);
    k_embed<<<(N_NODES + EMB_NODES - 1) / EMB_NODES, 256>>>(x, W_embed, b_embed);

    float* whi = nullptr; float* wlo = nullptr;
    cudaGetSymbolAddress((void**)&whi, g_Whi);
    cudaGetSymbolAddress((void**)&wlo, g_Wlo);

    dim3 ggrid(GBN == 128 ? 2 : 1, (N_NODES + GBM - 1) / GBM);
    int agg_blocks = (N_NODES * 32 + 255) / 256;

    // layer 1: g_b = g_a @ W1 ; g_a = relu(agg(g_b) + b1)
    k_gemm_tc<<<ggrid, 256>>>(whi, wlo);
    k_agg<true, true><<<agg_blocks, 256>>>(b1, nullptr);

    // layer 2: g_b = g_a @ W2 ; out = agg(g_b) + b2
    k_gemm_tc<<<ggrid, 256>>>(whi + D * D, wlo + D * D);
    k_agg<false, false><<<agg_blocks, 256>>>(b2, out);
}

// round 5
// speedup vs baseline: 1.6703x; 1.3222x over previous
#include <cuda_runtime.h>
#include <cuda_bf16.h>
#include <cstdint>

#define N_NODES 50000
#define N_EDGES 300000
#define D 256
#define F_IN 11
#define M_TILES 391
#define M_PAD (M_TILES * 128)

// ---------------- static scratch ------------------------------------------------
__device__ __align__(16) __nv_bfloat16 g_a0[(size_t)M_PAD * D];  // A hi split
__device__ __align__(16) __nv_bfloat16 g_a1[(size_t)M_PAD * D];  // A lo split
__device__ __align__(16) float g_b[(size_t)N_NODES * D];         // GEMM output fp32
__device__ __align__(16) __nv_bfloat16 g_ws[2][2][D * D];        // W splits [layer][split][n*256+k]
__device__ float g_dis[N_NODES];
__device__ int   g_cnt[N_NODES];
__device__ int   g_rowptr[N_NODES + 1];
__device__ int   g_cursor[N_NODES];
__device__ int   g_col[N_EDGES];

// ---------------- helpers -------------------------------------------------------
__device__ __forceinline__ uint32_t smem_u32(const void* p) {
    uint32_t a;
    asm("{ .reg .u64 t; cvta.to.shared.u64 t, %1; cvt.u32.u64 %0, t; }" : "=r"(a) : "l"(p));
    return a;
}
__device__ __forceinline__ void cpa16(uint32_t d, const void* s) {
    asm volatile("cp.async.cg.shared.global [%0], [%1], 16;" :: "r"(d), "l"(s));
}
__device__ __forceinline__ void ldsm4(uint32_t* r, uint32_t a) {
    asm volatile("ldmatrix.sync.aligned.m8n8.x4.shared.b16 {%0,%1,%2,%3}, [%4];"
                 : "=r"(r[0]), "=r"(r[1]), "=r"(r[2]), "=r"(r[3]) : "r"(a));
}
__device__ __forceinline__ void mma16(float* c, const uint32_t* a, const uint32_t* b) {
    asm volatile("mma.sync.aligned.m16n8k16.row.col.f32.bf16.bf16.f32 "
                 "{%0,%1,%2,%3},{%4,%5,%6,%7},{%8,%9},{%0,%1,%2,%3};"
                 : "+f"(c[0]), "+f"(c[1]), "+f"(c[2]), "+f"(c[3])
                 : "r"(a[0]), "r"(a[1]), "r"(a[2]), "r"(a[3]), "r"(b[0]), "r"(b[1]));
}
__device__ __forceinline__ void split2(float x, __nv_bfloat16& s0, __nv_bfloat16& s1) {
    s0 = __float2bfloat16(x);
    s1 = __float2bfloat16(x - __bfloat162float(s0));
}

// ---------------- CSR build -----------------------------------------------------
__global__ void k_zero_cnt() {
    int i = blockIdx.x * blockDim.x + threadIdx.x;
    if (i < N_NODES) g_cnt[i] = 0;
}
__global__ void k_count(const int* __restrict__ ei) {
    int e = blockIdx.x * blockDim.x + threadIdx.x;
    if (e < N_EDGES) atomicAdd(&g_cnt[ei[N_EDGES + e]], 1);
}
__global__ void k_scan() {
    __shared__ int part[1024];
    int t = threadIdx.x;
    const int CH = (N_NODES + 1023) / 1024;
    int lo = t * CH, hi = min(lo + CH, N_NODES);
    int s = 0;
    for (int i = lo; i < hi; i++) s += g_cnt[i];
    part[t] = s;
    __syncthreads();
    for (int off = 1; off < 1024; off <<= 1) {
        int tmp = (t >= off) ? part[t - off] : 0;
        __syncthreads();
        part[t] += tmp;
        __syncthreads();
    }
    int run = part[t] - s;
    for (int i = lo; i < hi; i++) {
        g_rowptr[i] = run;
        g_cursor[i] = run;
        int c = g_cnt[i];
        g_dis[i] = rsqrtf((float)(c + 1));
        run += c;
    }
    if (t == 0) g_rowptr[N_NODES] = N_EDGES;
}
__global__ void k_fill(const int* __restrict__ ei) {
    int e = blockIdx.x * blockDim.x + threadIdx.x;
    if (e < N_EDGES) {
        int d = ei[N_EDGES + e];
        int p = atomicAdd(&g_cursor[d], 1);
        g_col[p] = ei[e];
    }
}

// ---------------- weight split: W[k][n] -> g_ws[l][s][n*256+k] ------------------
__global__ void k_wsplit(const float* __restrict__ W1, const float* __restrict__ W2) {
    int i = blockIdx.x * 256 + threadIdx.x;   // i = k*256+n
    int k = i >> 8, n = i & 255;
    __nv_bfloat16 s0, s1;
    split2(W1[i], s0, s1);
    g_ws[0][0][n * 256 + k] = s0; g_ws[0][1][n * 256 + k] = s1;
    split2(W2[i], s0, s1);
    g_ws[1][0][n * 256 + k] = s0; g_ws[1][1][n * 256 + k] = s1;
}

// ---------------- embed: g_a0/g_a1 = split2(relu(x @ W_embed + b)), pad zeros ---
#define EMB_NODES 8
__global__ __launch_bounds__(256) void k_embed(const float* __restrict__ x,
                                               const float* __restrict__ W,
                                               const float* __restrict__ b) {
    __shared__ float Ws[F_IN * D];
    __shared__ float xs[EMB_NODES * F_IN];
    int t = threadIdx.x;
    for (int i = t; i < F_IN * D; i += 256) Ws[i] = W[i];
    int n0 = blockIdx.x * EMB_NODES;
    for (int i = t; i < EMB_NODES * F_IN; i += 256) {
        int node = n0 + i / F_IN;
        xs[i] = (node < N_NODES) ? x[(size_t)node * F_IN + (i % F_IN)] : 0.0f;
    }
    __syncthreads();
    float bv = b[t];
    #pragma unroll 1
    for (int j = 0; j < EMB_NODES; j++) {
        int node = n0 + j;
        if (node >= M_PAD) break;
        __nv_bfloat16 s0 = __float2bfloat16(0.0f), s1 = s0;
        if (node < N_NODES) {
            float acc = bv;
            #pragma unroll
            for (int k = 0; k < F_IN; k++) acc += xs[j * F_IN + k] * Ws[k * D + t];
            split2(fmaxf(acc, 0.0f), s0, s1);
        }
        size_t idx = (size_t)node * D + t;
        g_a0[idx] = s0;
        g_a1[idx] = s1;
    }
}

// ---------------- bf16x2 mma.sync GEMM ------------------------------------------
// grid 148 persistent CTAs: nh = cta&1 (N half), m-tiles stride 74.
// smem: B resident [2 splits][128 n][256 k] = 128KB; A double-buffered chunks
// [2 buf][2 splits][128 m][64 k] = 64KB.
#define SMEM_B_OFF 0
#define SMEM_A_OFF 131072
#define SMEM_GEMM  196608

__device__ __forceinline__ void load_achunk(uint32_t sb, int t, int m0, int k0, int buf) {
    #pragma unroll
    for (int j = 0; j < 8; j++) {
        int u = t + 256 * j;
        int s = u >> 10;
        int row = (u & 1023) >> 3;
        int q = u & 7;
        uint32_t dst = sb + SMEM_A_OFF + buf * 32768 + s * 16384 + row * 128 + ((q ^ (row & 7)) << 4);
        const __nv_bfloat16* src = (s ? g_a1 : g_a0) + (size_t)(m0 + row) * D + k0 + q * 8;
        cpa16(dst, src);
    }
    asm volatile("cp.async.commit_group;" ::: "memory");
}

__global__ __launch_bounds__(256, 1) void k_gemm_bf16(const __nv_bfloat16* __restrict__ Wb,
                                                      float* __restrict__ out) {
    extern __shared__ __align__(1024) char smem[];
    const uint32_t sb = smem_u32(smem);
    const int t = threadIdx.x, wid = t >> 5, lane = t & 31;
    const int nh = blockIdx.x & 1;
    const int wm = wid & 3, wn = wid >> 2;
    const int dq = lane >> 3, Lr = lane & 7;

    // load resident B (both splits of this N-half), one commit group
    #pragma unroll
    for (int j = 0; j < 32; j++) {
        int u = t + 256 * j;
        int s = u >> 12;
        int row = (u & 4095) >> 5;
        int q = u & 31;
        uint32_t dst = sb + SMEM_B_OFF + s * 65536 + row * 512 + ((q ^ (row & 7)) << 4);
        const void* src = Wb + s * (D * D) + (nh * 128 + row) * D + q * 8;
        cpa16(dst, src);
    }
    asm volatile("cp.async.commit_group;" ::: "memory");

    // precomputed lane geometry
    int rowA[2], xorA[2];
    #pragma unroll
    for (int it = 0; it < 2; it++) {
        rowA[it] = wm * 32 + it * 16 + Lr + (dq & 1) * 8;
        xorA[it] = rowA[it] & 7;
    }
    int qhiA = dq >> 1;
    int rowB[4], xorB[4];
    #pragma unroll
    for (int g4 = 0; g4 < 4; g4++) {
        rowB[g4] = wn * 64 + g4 * 16 + (dq >> 1) * 8 + Lr;
        xorB[g4] = rowB[g4] & 7;
    }
    int qhiB = dq & 1;

    #pragma unroll 1
    for (int mt = blockIdx.x >> 1; mt < M_TILES; mt += 74) {
        int m0 = mt * 128;
        float C[2][8][4];
        #pragma unroll
        for (int it = 0; it < 2; it++)
            #pragma unroll
            for (int f = 0; f < 8; f++)
                #pragma unroll
                for (int q = 0; q < 4; q++) C[it][f][q] = 0.0f;

        load_achunk(sb, t, m0, 0, 0);
        load_achunk(sb, t, m0, 64, 1);

        #pragma unroll 1
        for (int c = 0; c < 4; c++) {
            if (c < 3) asm volatile("cp.async.wait_group 1;" ::: "memory");
            else       asm volatile("cp.async.wait_group 0;" ::: "memory");
            __syncthreads();
            uint32_t Ab = sb + SMEM_A_OFF + (c & 1) * 32768;

            #pragma unroll
            for (int kl = 0; kl < 4; kl++) {
                int ks = c * 4 + kl;
                uint32_t ah[2][4], al[2][4];
                #pragma unroll
                for (int it = 0; it < 2; it++) {
                    int qa = kl * 2 + qhiA;
                    uint32_t addr = Ab + rowA[it] * 128 + ((qa ^ xorA[it]) << 4);
                    ldsm4(ah[it], addr);
                    ldsm4(al[it], addr + 16384);
                }
                uint32_t bh[8][2], bl[8][2];
                #pragma unroll
                for (int g4 = 0; g4 < 4; g4++) {
                    int qb = ks * 2 + qhiB;
                    uint32_t addr = sb + SMEM_B_OFF + rowB[g4] * 512 + ((qb ^ xorB[g4]) << 4);
                    uint32_t r[4];
                    ldsm4(r, addr);
                    bh[2 * g4][0] = r[0]; bh[2 * g4][1] = r[1];
                    bh[2 * g4 + 1][0] = r[2]; bh[2 * g4 + 1][1] = r[3];
                    ldsm4(r, addr + 65536);
                    bl[2 * g4][0] = r[0]; bl[2 * g4][1] = r[1];
                    bl[2 * g4 + 1][0] = r[2]; bl[2 * g4 + 1][1] = r[3];
                }
                #pragma unroll
                for (int it = 0; it < 2; it++)
                    #pragma unroll
                    for (int f = 0; f < 8; f++) {
                        mma16(C[it][f], ah[it], bh[f]);
                        mma16(C[it][f], ah[it], bl[f]);
                        mma16(C[it][f], al[it], bh[f]);
                    }
            }
            __syncthreads();
            if (c < 2) load_achunk(sb, t, m0, (c + 2) * 64, c & 1);
        }

        // epilogue: direct gmem stores from c-frags
        #pragma unroll
        for (int it = 0; it < 2; it++) {
            int m = m0 + wm * 32 + it * 16 + (lane >> 2);
            #pragma unroll
            for (int f = 0; f < 8; f++) {
                int col = nh * 128 + wn * 64 + f * 8 + (lane & 3) * 2;
                if (m < N_NODES)
                    *(float2*)(out + (size_t)m * D + col) = make_float2(C[it][f][0], C[it][f][1]);
                if (m + 8 < N_NODES)
                    *(float2*)(out + (size_t)(m + 8) * D + col) = make_float2(C[it][f][2], C[it][f][3]);
            }
        }
    }
}

// ---------------- aggregation: gather over CSR ----------------------------------
// out[i] = bias + dis[i]^2 * hw[i] + sum_{e: dst=i} dis[i]*dis[src] * hw[src]
template<bool RELU, bool TO_SPLITS>
__global__ __launch_bounds__(256) void k_agg(const float* __restrict__ bias,
                                             float* __restrict__ out_ext) {
    int gw = (blockIdx.x * 256 + threadIdx.x) >> 5;
    int lane = threadIdx.x & 31;
    if (gw >= N_NODES) return;
    const float* hw = g_b;
    float dd = g_dis[gw];
    int c0 = lane * 8;
    const float4* hp = (const float4*)(hw + (size_t)gw * D + c0);
    float4 h0 = hp[0], h1 = hp[1];
    float4 bb0 = *(const float4*)(bias + c0);
    float4 bb1 = *(const float4*)(bias + c0 + 4);
    float sw = dd * dd;
    float v[8];
    v[0] = bb0.x + h0.x * sw; v[1] = bb0.y + h0.y * sw;
    v[2] = bb0.z + h0.z * sw; v[3] = bb0.w + h0.w * sw;
    v[4] = bb1.x + h1.x * sw; v[5] = bb1.y + h1.y * sw;
    v[6] = bb1.z + h1.z * sw; v[7] = bb1.w + h1.w * sw;
    int e1 = g_rowptr[gw + 1];
    for (int e = g_rowptr[gw]; e < e1; e++) {
        int s = g_col[e];
        float w = dd * g_dis[s];
        const float4* pp = (const float4*)(hw + (size_t)s * D + c0);
        float4 v0 = pp[0], v1 = pp[1];
        v[0] += v0.x * w; v[1] += v0.y * w; v[2] += v0.z * w; v[3] += v0.w * w;
        v[4] += v1.x * w; v[5] += v1.y * w; v[6] += v1.z * w; v[7] += v1.w * w;
    }
    if (RELU) {
        #pragma unroll
        for (int i = 0; i < 8; i++) v[i] = fmaxf(v[i], 0.0f);
    }
    if (TO_SPLITS) {
        __align__(16) __nv_bfloat16 s0[8], s1[8];
        #pragma unroll
        for (int i = 0; i < 8; i++) split2(v[i], s0[i], s1[i]);
        size_t idx = (size_t)gw * D + c0;
        *(uint4*)&g_a0[idx] = *(const uint4*)s0;
        *(uint4*)&g_a1[idx] = *(const uint4*)s1;
    } else {
        float4* op = (float4*)(out_ext + (size_t)gw * D + c0);
        op[0] = make_float4(v[0], v[1], v[2], v[3]);
        op[1] = make_float4(v[4], v[5], v[6], v[7]);
    }
}

// ---------------- launch --------------------------------------------------------
extern "C" void kernel_launch(void* const* d_in, const int* in_sizes, int n_in,
                              void* d_out, int out_size) {
    const float* x       = (const float*)d_in[0];
    const int*   ei      = (const int*)d_in[1];
    const float* W_embed = (const float*)d_in[2];
    const float* b_embed = (const float*)d_in[3];
    const float* W1      = (const float*)d_in[4];
    const float* b1      = (const float*)d_in[5];
    const float* W2      = (const float*)d_in[6];
    const float* b2      = (const float*)d_in[7];
    float* out = (float*)d_out;

    cudaFuncSetAttribute(k_gemm_bf16, cudaFuncAttributeMaxDynamicSharedMemorySize, SMEM_GEMM);

    __nv_bfloat16* ws = nullptr;
    float* gb = nullptr;
    cudaGetSymbolAddress((void**)&ws, g_ws);
    cudaGetSymbolAddress((void**)&gb, g_b);

    int agg_blocks = (N_NODES * 32 + 255) / 256;

    // CSR + prep
    k_zero_cnt<<<(N_NODES + 255) / 256, 256>>>();
    k_count<<<(N_EDGES + 255) / 256, 256>>>(ei);
    k_scan<<<1, 1024>>>();
    k_fill<<<(N_EDGES + 255) / 256, 256>>>(ei);
    k_wsplit<<<(D * D) / 256, 256>>>(W1, W2);
    k_embed<<<(M_PAD + EMB_NODES - 1) / EMB_NODES, 256>>>(x, W_embed, b_embed);

    // layer 1
    k_gemm_bf16<<<148, 256, SMEM_GEMM>>>(ws, gb);
    k_agg<true, true><<<agg_blocks, 256>>>(b1, nullptr);

    // layer 2
    k_gemm_bf16<<<148, 256, SMEM_GEMM>>>(ws + 2 * D * D, gb);
    k_agg<false, false><<<agg_blocks, 256>>>(b2, out);
}

// round 7
// speedup vs baseline: 2.3595x; 1.4126x over previous
#include <cuda_runtime.h>
#include <cuda_bf16.h>
#include <cstdint>

#define N_NODES 50000
#define N_EDGES 300000
#define D 256
#define F_IN 11
#define M_TILES 391
#define M_PAD (M_TILES * 128)

// ---------------- static scratch ------------------------------------------------
__device__ __align__(16) __nv_bfloat16 g_a0[(size_t)M_PAD * D];  // A hi split
__device__ __align__(16) __nv_bfloat16 g_a1[(size_t)M_PAD * D];  // A lo split
__device__ __align__(16) float g_b[(size_t)N_NODES * D];         // GEMM output fp32
__device__ __align__(16) __nv_bfloat16 g_ws[2][2][D * D];        // W splits [layer][split][n*256+k]
__device__ float g_dis[N_NODES];
__device__ int   g_cnt[N_NODES];
__device__ int   g_rowptr[N_NODES + 1];
__device__ int   g_cursor[N_NODES];
__device__ int   g_col[N_EDGES];
__device__ int   g_part[64];
__device__ int   g_poff[64];

// ---------------- helpers -------------------------------------------------------
__device__ __forceinline__ uint32_t smem_u32(const void* p) {
    uint32_t a;
    asm("{ .reg .u64 t; cvta.to.shared.u64 t, %1; cvt.u32.u64 %0, t; }" : "=r"(a) : "l"(p));
    return a;
}
__device__ __forceinline__ void cpa16(uint32_t d, const void* s) {
    asm volatile("cp.async.cg.shared.global [%0], [%1], 16;" :: "r"(d), "l"(s));
}
__device__ __forceinline__ void ldsm4(uint32_t* r, uint32_t a) {
    asm volatile("ldmatrix.sync.aligned.m8n8.x4.shared.b16 {%0,%1,%2,%3}, [%4];"
                 : "=r"(r[0]), "=r"(r[1]), "=r"(r[2]), "=r"(r[3]) : "r"(a));
}
__device__ __forceinline__ void mma16(float* c, const uint32_t* a, const uint32_t* b) {
    asm volatile("mma.sync.aligned.m16n8k16.row.col.f32.bf16.bf16.f32 "
                 "{%0,%1,%2,%3},{%4,%5,%6,%7},{%8,%9},{%0,%1,%2,%3};"
                 : "+f"(c[0]), "+f"(c[1]), "+f"(c[2]), "+f"(c[3])
                 : "r"(a[0]), "r"(a[1]), "r"(a[2]), "r"(a[3]), "r"(b[0]), "r"(b[1]));
}
__device__ __forceinline__ void split2(float x, __nv_bfloat16& s0, __nv_bfloat16& s1) {
    s0 = __float2bfloat16(x);
    s1 = __float2bfloat16(x - __bfloat162float(s0));
}

// ---------------- prep: zero counts + weight split ------------------------------
__global__ void k_prep(const float* __restrict__ W1, const float* __restrict__ W2) {
    int i = blockIdx.x * 256 + threadIdx.x;   // 0..65535, i = k*256+n
    if (i < N_NODES) g_cnt[i] = 0;
    int k = i >> 8, n = i & 255;
    __nv_bfloat16 s0, s1;
    split2(W1[i], s0, s1);
    g_ws[0][0][n * 256 + k] = s0; g_ws[0][1][n * 256 + k] = s1;
    split2(W2[i], s0, s1);
    g_ws[1][0][n * 256 + k] = s0; g_ws[1][1][n * 256 + k] = s1;
}

// ---------------- CSR build -----------------------------------------------------
__global__ void k_count(const int* __restrict__ ei) {
    int e = blockIdx.x * blockDim.x + threadIdx.x;
    if (e < N_EDGES) atomicAdd(&g_cnt[ei[N_EDGES + e]], 1);
}

// distributed scan: A) per-block scan + partials, B) scan partials, C) apply
#define SCAN_BLKS 49
__global__ __launch_bounds__(1024) void k_scan_a() {
    __shared__ int s[1024];
    int t = threadIdx.x, i = blockIdx.x * 1024 + t;
    int v = (i < N_NODES) ? g_cnt[i] : 0;
    s[t] = v;
    __syncthreads();
    #pragma unroll
    for (int off = 1; off < 1024; off <<= 1) {
        int tmp = (t >= off) ? s[t - off] : 0;
        __syncthreads();
        s[t] += tmp;
        __syncthreads();
    }
    if (i < N_NODES) g_rowptr[i] = s[t] - v;   // block-local exclusive
    if (t == 1023) g_part[blockIdx.x] = s[t];
}
__global__ void k_scan_b() {
    __shared__ int s[64];
    int t = threadIdx.x;
    int v = (t < SCAN_BLKS) ? g_part[t] : 0;
    s[t] = v;
    __syncthreads();
    #pragma unroll
    for (int off = 1; off < 64; off <<= 1) {
        int tmp = (t >= off) ? s[t - off] : 0;
        __syncthreads();
        s[t] += tmp;
        __syncthreads();
    }
    if (t < SCAN_BLKS) g_poff[t] = s[t] - v;
}
__global__ __launch_bounds__(1024) void k_scan_c() {
    int t = threadIdx.x, i = blockIdx.x * 1024 + t;
    if (i < N_NODES) {
        int r = g_rowptr[i] + g_poff[blockIdx.x];
        g_rowptr[i] = r;
        g_cursor[i] = r;
        g_dis[i] = rsqrtf((float)(g_cnt[i] + 1));
    }
    if (i == N_NODES) g_rowptr[N_NODES] = N_EDGES;
}
__global__ void k_fill(const int* __restrict__ ei) {
    int e = blockIdx.x * blockDim.x + threadIdx.x;
    if (e < N_EDGES) {
        int d = ei[N_EDGES + e];
        int p = atomicAdd(&g_cursor[d], 1);
        g_col[p] = ei[e];
    }
}

// ---------------- embed: g_a0/g_a1 = split2(relu(x @ W_embed + b)), pad zeros ---
#define EMB_NODES 8
__global__ __launch_bounds__(256) void k_embed(const float* __restrict__ x,
                                               const float* __restrict__ W,
                                               const float* __restrict__ b) {
    __shared__ float Ws[F_IN * D];
    __shared__ float xs[EMB_NODES * F_IN];
    int t = threadIdx.x;
    for (int i = t; i < F_IN * D; i += 256) Ws[i] = W[i];
    int n0 = blockIdx.x * EMB_NODES;
    for (int i = t; i < EMB_NODES * F_IN; i += 256) {
        int node = n0 + i / F_IN;
        xs[i] = (node < N_NODES) ? x[(size_t)node * F_IN + (i % F_IN)] : 0.0f;
    }
    __syncthreads();
    float bv = b[t];
    #pragma unroll 1
    for (int j = 0; j < EMB_NODES; j++) {
        int node = n0 + j;
        if (node >= M_PAD) break;
        __nv_bfloat16 s0 = __float2bfloat16(0.0f), s1 = s0;
        if (node < N_NODES) {
            float acc = bv;
            #pragma unroll
            for (int k = 0; k < F_IN; k++) acc += xs[j * F_IN + k] * Ws[k * D + t];
            split2(fmaxf(acc, 0.0f), s0, s1);
        }
        size_t idx = (size_t)node * D + t;
        g_a0[idx] = s0;
        g_a1[idx] = s1;
    }
}

// ---------------- bf16x2 mma.sync GEMM, 2 CTAs/SM -------------------------------
// grid 296 persistent CTAs: nq = cta&3 (N quarter, 64 cols), m-tiles stride 74.
// smem 96KB: B resident [2 spl][64 n][256 k] = 64KB at 0;
//            A double buf [2][128 m][128B: hi 64B | lo 64B] = 32KB at 65536.
#define SMEM_A_OFF 65536
#define SMEM_GEMM  98304

__device__ __forceinline__ void load_achunk(uint32_t sb, int t, int m0, int k0, int buf) {
    #pragma unroll
    for (int j = 0; j < 4; j++) {
        int u = t + 256 * j;                  // 0..1023 16B units
        int row = u >> 3, uu = u & 7;         // uu<4: hi, else lo
        uint32_t dst = sb + SMEM_A_OFF + buf * 16384 + row * 128 + ((uu ^ (row & 7)) << 4);
        const __nv_bfloat16* base = (uu < 4) ? g_a0 : g_a1;
        cpa16(dst, base + (size_t)(m0 + row) * D + k0 + (uu & 3) * 8);
    }
    asm volatile("cp.async.commit_group;" ::: "memory");
}

__global__ __launch_bounds__(256, 2) void k_gemm_bf16(const __nv_bfloat16* __restrict__ Wb,
                                                      float* __restrict__ out) {
    extern __shared__ __align__(1024) char smem[];
    const uint32_t sb = smem_u32(smem);
    const int t = threadIdx.x, wid = t >> 5, lane = t & 31;
    const int nq = blockIdx.x & 3;
    const int wm = wid & 3, wn = wid >> 2;
    const int dq = lane >> 3, Lr = lane & 7;

    // load resident B (quarter of W, both splits), one commit group
    #pragma unroll
    for (int j = 0; j < 16; j++) {
        int u = t + 256 * j;                  // 0..4095 16B units
        int s = u >> 11;
        int row = (u & 2047) >> 5;
        int q = u & 31;
        uint32_t dst = sb + s * 32768 + row * 512 + ((q ^ (row & 7)) << 4);
        cpa16(dst, Wb + s * (D * D) + (size_t)(nq * 64 + row) * D + q * 8);
    }
    asm volatile("cp.async.commit_group;" ::: "memory");

    // lane geometry
    int rowA[2], xorA[2];
    #pragma unroll
    for (int it = 0; it < 2; it++) {
        rowA[it] = wm * 32 + it * 16 + Lr + (dq & 1) * 8;
        xorA[it] = rowA[it] & 7;
    }
    int uhiA = dq >> 1;
    int rowB[2], xorB[2];
    #pragma unroll
    for (int g4 = 0; g4 < 2; g4++) {
        rowB[g4] = wn * 32 + g4 * 16 + (dq >> 1) * 8 + Lr;
        xorB[g4] = rowB[g4] & 7;
    }
    int qloB = dq & 1;

    #pragma unroll 1
    for (int mt = blockIdx.x >> 2; mt < M_TILES; mt += 74) {
        int m0 = mt * 128;
        float C[2][4][4];
        #pragma unroll
        for (int it = 0; it < 2; it++)
            #pragma unroll
            for (int f = 0; f < 4; f++)
                #pragma unroll
                for (int q = 0; q < 4; q++) C[it][f][q] = 0.0f;

        load_achunk(sb, t, m0, 0, 0);
        load_achunk(sb, t, m0, 32, 1);

        #pragma unroll 1
        for (int c = 0; c < 8; c++) {
            if (c < 7) asm volatile("cp.async.wait_group 1;" ::: "memory");
            else       asm volatile("cp.async.wait_group 0;" ::: "memory");
            __syncthreads();
            uint32_t Ab = sb + SMEM_A_OFF + (c & 1) * 16384;

            #pragma unroll
            for (int kl = 0; kl < 2; kl++) {
                int ks = c * 2 + kl;
                uint32_t ah[2][4], al[2][4];
                #pragma unroll
                for (int it = 0; it < 2; it++) {
                    int uh = kl * 2 + uhiA;
                    uint32_t base = Ab + rowA[it] * 128;
                    ldsm4(ah[it], base + ((uh ^ xorA[it]) << 4));
                    ldsm4(al[it], base + (((uh + 4) ^ xorA[it]) << 4));
                }
                uint32_t bh[4][2], bl[4][2];
                #pragma unroll
                for (int g4 = 0; g4 < 2; g4++) {
                    int qb = ks * 2 + qloB;
                    uint32_t base = sb + rowB[g4] * 512 + ((qb ^ xorB[g4]) << 4);
                    uint32_t r[4];
                    ldsm4(r, base);
                    bh[2 * g4][0] = r[0]; bh[2 * g4][1] = r[1];
                    bh[2 * g4 + 1][0] = r[2]; bh[2 * g4 + 1][1] = r[3];
                    ldsm4(r, base + 32768);
                    bl[2 * g4][0] = r[0]; bl[2 * g4][1] = r[1];
                    bl[2 * g4 + 1][0] = r[2]; bl[2 * g4 + 1][1] = r[3];
                }
                #pragma unroll
                for (int it = 0; it < 2; it++)
                    #pragma unroll
                    for (int f = 0; f < 4; f++) {
                        mma16(C[it][f], ah[it], bh[f]);
                        mma16(C[it][f], ah[it], bl[f]);
                        mma16(C[it][f], al[it], bh[f]);
                    }
            }
            __syncthreads();
            if (c < 6) load_achunk(sb, t, m0, (c + 2) * 32, c & 1);
        }

        // epilogue: direct gmem stores
        #pragma unroll
        for (int it = 0; it < 2; it++) {
            int m = m0 + wm * 32 + it * 16 + (lane >> 2);
            #pragma unroll
            for (int f = 0; f < 4; f++) {
                int col = nq * 64 + wn * 32 + f * 8 + (lane & 3) * 2;
                if (m < N_NODES)
                    *(float2*)(out + (size_t)m * D + col) = make_float2(C[it][f][0], C[it][f][1]);
                if (m + 8 < N_NODES)
                    *(float2*)(out + (size_t)(m + 8) * D + col) = make_float2(C[it][f][2], C[it][f][3]);
            }
        }
    }
}

// ---------------- aggregation: gather over CSR ----------------------------------
// out[i] = bias + dis[i]^2 * hw[i] + sum_{e: dst=i} dis[i]*dis[src] * hw[src]
template<bool RELU, bool TO_SPLITS>
__global__ __launch_bounds__(256) void k_agg(const float* __restrict__ bias,
                                             float* __restrict__ out_ext) {
    int gw = (blockIdx.x * 256 + threadIdx.x) >> 5;
    int lane = threadIdx.x & 31;
    if (gw >= N_NODES) return;
    const float* hw = g_b;
    float dd = g_dis[gw];
    int c0 = lane * 8;
    const float4* hp = (const float4*)(hw + (size_t)gw * D + c0);
    float4 h0 = hp[0], h1 = hp[1];
    float4 bb0 = *(const float4*)(bias + c0);
    float4 bb1 = *(const float4*)(bias + c0 + 4);
    float sw = dd * dd;
    float v[8];
    v[0] = bb0.x + h0.x * sw; v[1] = bb0.y + h0.y * sw;
    v[2] = bb0.z + h0.z * sw; v[3] = bb0.w + h0.w * sw;
    v[4] = bb1.x + h1.x * sw; v[5] = bb1.y + h1.y * sw;
    v[6] = bb1.z + h1.z * sw; v[7] = bb1.w + h1.w * sw;
    int e = g_rowptr[gw], e1 = g_rowptr[gw + 1];
    // 2-way unrolled gather for MLP
    for (; e + 1 < e1; e += 2) {
        int s0 = g_col[e], s1 = g_col[e + 1];
        float w0 = dd * g_dis[s0], w1 = dd * g_dis[s1];
        const float4* p0 = (const float4*)(hw + (size_t)s0 * D + c0);
        const float4* p1 = (const float4*)(hw + (size_t)s1 * D + c0);
        float4 x0 = p0[0], x1 = p0[1];
        float4 y0 = p1[0], y1 = p1[1];
        v[0] += x0.x * w0 + y0.x * w1; v[1] += x0.y * w0 + y0.y * w1;
        v[2] += x0.z * w0 + y0.z * w1; v[3] += x0.w * w0 + y0.w * w1;
        v[4] += x1.x * w0 + y1.x * w1; v[5] += x1.y * w0 + y1.y * w1;
        v[6] += x1.z * w0 + y1.z * w1; v[7] += x1.w * w0 + y1.w * w1;
    }
    if (e < e1) {
        int s0 = g_col[e];
        float w0 = dd * g_dis[s0];
        const float4* p0 = (const float4*)(hw + (size_t)s0 * D + c0);
        float4 x0 = p0[0], x1 = p0[1];
        v[0] += x0.x * w0; v[1] += x0.y * w0; v[2] += x0.z * w0; v[3] += x0.w * w0;
        v[4] += x1.x * w0; v[5] += x1.y * w0; v[6] += x1.z * w0; v[7] += x1.w * w0;
    }
    if (RELU) {
        #pragma unroll
        for (int i = 0; i < 8; i++) v[i] = fmaxf(v[i], 0.0f);
    }
    if (TO_SPLITS) {
        __align__(16) __nv_bfloat16 s0[8], s1[8];
        #pragma unroll
        for (int i = 0; i < 8; i++) split2(v[i], s0[i], s1[i]);
        size_t idx = (size_t)gw * D + c0;
        *(uint4*)&g_a0[idx] = *(const uint4*)s0;
        *(uint4*)&g_a1[idx] = *(const uint4*)s1;
    } else {
        float4* op = (float4*)(out_ext + (size_t)gw * D + c0);
        op[0] = make_float4(v[0], v[1], v[2], v[3]);
        op[1] = make_float4(v[4], v[5], v[6], v[7]);
    }
}

// ---------------- launch --------------------------------------------------------
extern "C" void kernel_launch(void* const* d_in, const int* in_sizes, int n_in,
                              void* d_out, int out_size) {
    const float* x       = (const float*)d_in[0];
    const int*   ei      = (const int*)d_in[1];
    const float* W_embed = (const float*)d_in[2];
    const float* b_embed = (const float*)d_in[3];
    const float* W1      = (const float*)d_in[4];
    const float* b1      = (const float*)d_in[5];
    const float* W2      = (const float*)d_in[6];
    const float* b2      = (const float*)d_in[7];
    float* out = (float*)d_out;

    cudaFuncSetAttribute(k_gemm_bf16, cudaFuncAttributeMaxDynamicSharedMemorySize, SMEM_GEMM);

    __nv_bfloat16* ws = nullptr;
    float* gb = nullptr;
    cudaGetSymbolAddress((void**)&ws, g_ws);
    cudaGetSymbolAddress((void**)&gb, g_b);

    int agg_blocks = (N_NODES * 32 + 255) / 256;

    // slots 1-3: prep (gemm lands at slot 4 = ncu capture slot)
    k_prep<<<(D * D) / 256, 256>>>(W1, W2);
    k_embed<<<(M_PAD + EMB_NODES - 1) / EMB_NODES, 256>>>(x, W_embed, b_embed);
    k_count<<<(N_EDGES + 255) / 256, 256>>>(ei);

    // layer 1 GEMM (slot 4)
    k_gemm_bf16<<<296, 256, SMEM_GEMM>>>(ws, gb);

    // CSR finish (independent of GEMM)
    k_scan_a<<<SCAN_BLKS, 1024>>>();
    k_scan_b<<<1, 64>>>();
    k_scan_c<<<SCAN_BLKS, 1024>>>();
    k_fill<<<(N_EDGES + 255) / 256, 256>>>(ei);

    // layer 1 aggregation -> splits for layer 2
    k_agg<true, true><<<agg_blocks, 256>>>(b1, nullptr);

    // layer 2
    k_gemm_bf16<<<296, 256, SMEM_GEMM>>>(ws + 2 * D * D, gb);
    k_agg<false, false><<<agg_blocks, 256>>>(b2, out);
}